// round 17
// baseline (speedup 1.0000x reference)
#include <cuda_runtime.h>
#include <math.h>
#include <stdint.h>

#define B_   128
#define T_   512
#define F_   512
#define U_   256
#define NROW 65536        // T*B
#define NB   256          // 2*B (fwd+bwd batched)
#define RING 8
#define RSZ  (NB * U_)    // 65536
#define NCTA 128          // persistent grid <= SM count => co-resident

typedef unsigned long long ull;

// ---------------- f32x2 packed-FMA helpers (sm_100+: 2 FMA per issue slot) ----
__device__ __forceinline__ ull pack2(float lo, float hi) {
    ull r; asm("mov.b64 %0, {%1, %2};" : "=l"(r) : "f"(lo), "f"(hi)); return r;
}
__device__ __forceinline__ ull fma2(ull a, ull b, ull c) {
    ull d; asm("fma.rn.f32x2 %0, %1, %2, %3;" : "=l"(d) : "l"(a), "l"(b), "l"(c)); return d;
}
__device__ __forceinline__ void unpack2(ull v, float& lo, float& hi) {
    asm("mov.b64 {%0, %1}, %2;" : "=f"(lo), "=f"(hi) : "l"(v));
}

// ---------------- scratch (__device__ globals; no allocation allowed) ---------
__device__ float g_xT [(size_t)NROW * F_];
__device__ float g_xg [(size_t)NROW * 1024];
__device__ float g_xh [(size_t)NROW * U_];
__device__ float g_xc [(size_t)NROW * U_];
__device__ float g_outs[(size_t)NROW * 512];
__device__ float g_c1 [(size_t)NROW * U_];
__device__ float g_c2 [(size_t)NROW * U_];
__device__ float g_H   [RING * RSZ];
__device__ float g_C   [RING * RSZ];
__device__ float g_QH  [RING * RSZ];     // h_k @ Wh_state
__device__ float g_QC  [RING * RSZ];     // c_k @ Wc_state
__device__ float g_QC4H[RING * RSZ];     // c_k @ Wh_state (4th c-slot uses Wh)
__device__ float g_spart[NB * 8 * 8];    // score partials [row][nt][8]
__device__ float4 g_rk4 [U_ * U_];       // rk: [k][j] -> (i,f,m,o) = 2 f32x2 pairs
__device__ float2 g_att2[U_ * U_];       // [k][j] -> (Wh_state, Wc_state)
__device__ unsigned g_count;             // cumulative barrier counter

__device__ __forceinline__ float hsig(float x) {
    return fminf(fmaxf(0.2f * x + 0.5f, 0.f), 1.f);
}
__device__ __forceinline__ float t2(float x) { float t = tanhf(x); return t * t; }

// ---------------- per-launch init ---------------------------------------------
__global__ void k_zero() {
    int i = blockIdx.x * blockDim.x + threadIdx.x;
    if (i < RING * RSZ) {
        g_H[i] = 0.f; g_C[i] = 0.f;
        g_QH[i] = 0.f; g_QC[i] = 0.f; g_QC4H[i] = 0.f;
    }
    if (i < NB * 64) g_spart[i] = 0.f;
    if (i == 0) g_count = 0u;
}

// ---------------- permute x (b,t,f) -> (t,b,f) --------------------------------
__global__ void k_permute(const float* __restrict__ x) {
    int r = blockIdx.x;                 // r = t*128 + b
    int t = r >> 7, b = r & 127;
    const float4* src = (const float4*)(x + ((size_t)b * T_ + t) * F_);
    float4* dst = (float4*)(g_xT + (size_t)r * F_);
    dst[threadIdx.x] = src[threadIdx.x];
}

// ---------------- weight prep --------------------------------------------------
__global__ void k_prep_rk(const float* __restrict__ rk) {
    int k = blockIdx.x, j = threadIdx.x;
    g_rk4[k * U_ + j] = make_float4(rk[k * 1024 + j],
                                    rk[k * 1024 + 256 + j],
                                    rk[k * 1024 + 512 + j],
                                    rk[k * 1024 + 768 + j]);
}
__global__ void k_prep_att(const float* __restrict__ att_h, const float* __restrict__ att_c) {
    int k = blockIdx.x, j = threadIdx.x;
    g_att2[k * U_ + j] = make_float2(att_h[k * U_ + j], att_c[k * U_ + j]);
}

// ---------------- t=0 score partials (states are zero => scores from x only) --
__global__ void k_initss() {
    __shared__ float red[8][2];
    int row = blockIdx.x, j = threadIdx.x;
    int dir = row >> 7, bb = row & 127;
    int td0 = dir ? (T_ - 1) : 0;
    size_t xb = (size_t)(td0 * B_ + bb) * U_ + j;
    float sh = t2(g_xh[xb]);
    float sc = t2(g_xc[xb]);
#pragma unroll
    for (int o = 16; o > 0; o >>= 1) {
        sh += __shfl_down_sync(0xffffffffu, sh, o);
        sc += __shfl_down_sync(0xffffffffu, sc, o);
    }
    int lane = j & 31, w = j >> 5;
    if (lane == 0) { red[w][0] = sh; red[w][1] = sc; }
    __syncthreads();
    if (j == 0) {
        float Sh = 0.f, Sc = 0.f;
#pragma unroll
        for (int ww = 0; ww < 8; ww++) { Sh += red[ww][0]; Sc += red[ww][1]; }
        red[0][0] = Sh; red[0][1] = Sc;
    }
    __syncthreads();
    float Sh = red[0][0], Sc = red[0][1];
    if (j < 64) {
        int q = j >> 3, st = j & 7;
        float v = 0.f;
        if (q == 0) v = (st < 4 || st == 7) ? Sh : Sc;   // 4th c-score uses Wh -> xh
        g_spart[(row * 8 + q) * 8 + st] = v;
    }
}

// ---------------- 128x128x8 SGEMM with f32x2 packed FMA -----------------------
__global__ void k_sgemm(const float* __restrict__ A, const float* __restrict__ W,
                        float* __restrict__ C, int M, int N, int K, int lda, int ldw) {
    __shared__ float As[8][128];
    __shared__ float Bs[8][128];
    int tid = threadIdx.x;
    int bm = blockIdx.y, bn = blockIdx.x;
    const float* Ablk = A + (size_t)bm * 128 * lda;
    const float* Wblk = W + bn * 128;
    ull acc2[8][4];
#pragma unroll
    for (int i = 0; i < 8; i++)
#pragma unroll
        for (int j = 0; j < 4; j++) acc2[i][j] = 0ull;
    int aRow = tid >> 1, aCol = (tid & 1) * 4;
    int bRow = tid >> 5, bCol = (tid & 31) * 4;
    int tx = tid & 15, ty = tid >> 4;
    for (int k0 = 0; k0 < K; k0 += 8) {
        float4 av = *(const float4*)(Ablk + (size_t)aRow * lda + k0 + aCol);
        As[aCol + 0][aRow] = av.x; As[aCol + 1][aRow] = av.y;
        As[aCol + 2][aRow] = av.z; As[aCol + 3][aRow] = av.w;
        float4 bv = *(const float4*)(Wblk + (size_t)(k0 + bRow) * ldw + bCol);
        *(float4*)&Bs[bRow][bCol] = bv;
        __syncthreads();
#pragma unroll
        for (int kk = 0; kk < 8; kk++) {
            float4 a0 = *(const float4*)&As[kk][ty * 8];
            float4 a1 = *(const float4*)&As[kk][ty * 8 + 4];
            ull b2[4];
            b2[0] = *(const ull*)&Bs[kk][tx * 8 + 0];
            b2[1] = *(const ull*)&Bs[kk][tx * 8 + 2];
            b2[2] = *(const ull*)&Bs[kk][tx * 8 + 4];
            b2[3] = *(const ull*)&Bs[kk][tx * 8 + 6];
            float ra[8] = {a0.x, a0.y, a0.z, a0.w, a1.x, a1.y, a1.z, a1.w};
#pragma unroll
            for (int i = 0; i < 8; i++) {
                ull rp = pack2(ra[i], ra[i]);
#pragma unroll
                for (int jp = 0; jp < 4; jp++)
                    acc2[i][jp] = fma2(rp, b2[jp], acc2[i][jp]);
            }
        }
        __syncthreads();
    }
#pragma unroll
    for (int i = 0; i < 8; i++) {
        float o[8];
#pragma unroll
        for (int jp = 0; jp < 4; jp++) unpack2(acc2[i][jp], o[jp * 2], o[jp * 2 + 1]);
        size_t row = (size_t)(bm * 128 + ty * 8 + i);
        *(float4*)(C + row * N + bn * 128 + tx * 8)     = make_float4(o[0], o[1], o[2], o[3]);
        *(float4*)(C + row * N + bn * 128 + tx * 8 + 4) = make_float4(o[4], o[5], o[6], o[7]);
    }
}

// ---------------- cumulative grid barrier (R10-proven) ------------------------
__device__ __forceinline__ void gridbar(unsigned target) {
    __threadfence();
    __syncthreads();
    if (threadIdx.x == 0) {
        atomicAdd(&g_count, 1u);
        while (atomicAdd(&g_count, 0u) < target * (unsigned)NCTA) { __nanosleep(64); }
    }
    __syncthreads();
}

// ---------------- persistent recurrence: 2 phases / step, f32x2 math ----------
// 128 CTAs x 256 threads. CTA p: nt=p&7 -> j slice [nt*32,nt*32+32);
// mt=p>>3 -> rows [mt*16,mt*16+16). Scores for t+1 pipelined into Phase CQ.
__global__ void __launch_bounds__(256)
k_recur() {
    extern __shared__ char dsm[];
    float4* sW  = (float4*)dsm;                        // [k*32 + wj], 128KB
    ull*    sP  = (ull*)(dsm + 131072);                // BG: (hm,hm) pairs 16x264
    ull*    sH2 = (ull*)(dsm + 131072);                // CQ: (h_r, h_r+8) 8x264
    ull*    sC2 = (ull*)(dsm + 131072 + 16896);        // CQ: (c_r, c_r+8) 8x264
    __shared__ float sWts[16][8];
    __shared__ float sSw[8][16][8];                    // per-warp score partials

    const int p = blockIdx.x, tid = threadIdx.x;
    const int lane = tid & 31, wid = tid >> 5;
    const int nt = p & 7,  mt = p >> 3;
    const int J0 = nt * 32, R0 = mt * 16;
    const int jq = lane & 3, rr = lane >> 2;           // warp: 4 j x 8 rows
    const int wj = wid * 4 + jq;                       // 0..31 within slice
    const int jB = J0 + wj;                            // global unit index

    // one-time: rk4 slice -> smem (reused all 512 steps)
    for (int i = tid; i < 8192; i += 256) {
        int k = i >> 5, w = i & 31;
        sW[i] = g_rk4[k * U_ + J0 + w];
    }
    __syncthreads();

    for (int t = 0; t < T_; t++) {
        const int slot = t & 7;

        // ===== Phase BG: weights + hmix + gates GEMM + pointwise ==============
        if (tid < 128) {
            int r = tid >> 3, st = tid & 7;
            float s = 0.f;
#pragma unroll
            for (int q = 0; q < 8; q++)
                s += __ldcg(&g_spart[((R0 + r) * 8 + q) * 8 + st]);
            sWts[r][st] = sqrtf(s);
        }
        __syncthreads();
        if (tid < 32) {
            int r = tid >> 1, grp = (tid & 1) * 4;
            float a0 = sWts[r][grp], a1 = sWts[r][grp + 1];
            float a2 = sWts[r][grp + 2], a3 = sWts[r][grp + 3];
            float m = fmaxf(fmaxf(a0, a1), fmaxf(a2, a3));
            float e0 = expf(a0 - m), e1 = expf(a1 - m);
            float e2 = expf(a2 - m), e3 = expf(a3 - m);
            float inv = 1.f / (e0 + e1 + e2 + e3);
            sWts[r][grp] = e0 * inv; sWts[r][grp + 1] = e1 * inv;
            sWts[r][grp + 2] = e2 * inv; sWts[r][grp + 3] = e3 * inv;
        }
        __syncthreads();

        // hmix rows (16 x 256) into sP as duplicated pairs (hm,hm)
        for (int r = 0; r < 16; r++) {
            float hm = 0.f;
#pragma unroll
            for (int k = 1; k <= 4; k++)
                hm += sWts[r][k - 1] * __ldcg(&g_H[((t - k) & 7) * RSZ + (R0 + r) * U_ + tid]);
            hm = fmaxf(hm, 0.f);
            sP[r * 264 + tid] = pack2(hm, hm);
        }
        __syncthreads();
        {
            const ulonglong2* sW2 = (const ulonglong2*)sW;
            const ull* a0p = sP + rr * 264;
            const ull* a1p = sP + (rr + 8) * 264;
            ull accif0 = 0ull, accmo0 = 0ull, accif1 = 0ull, accmo1 = 0ull;
#pragma unroll 4
            for (int k = 0; k < U_; k++) {
                ulonglong2 w = sW2[k * 32 + wj];
                ull a0 = a0p[k], a1 = a1p[k];
                accif0 = fma2(a0, w.x, accif0);
                accmo0 = fma2(a0, w.y, accmo0);
                accif1 = fma2(a1, w.x, accif1);
                accmo1 = fma2(a1, w.y, accmo1);
            }
            float4 acc0, acc1;
            unpack2(accif0, acc0.x, acc0.y); unpack2(accmo0, acc0.z, acc0.w);
            unpack2(accif1, acc1.x, acc1.y); unpack2(accmo1, acc1.z, acc1.w);
#pragma unroll
            for (int pr = 0; pr < 2; pr++) {
                const float4 a = pr ? acc1 : acc0;
                const int lr = rr + pr * 8;
                const int row = R0 + lr;
                const int dir = row >> 7, bb = row & 127;
                const int td = dir ? (T_ - 1 - t) : t;
                const size_t xrow = (size_t)(td * B_ + bb) * 1024;
                float gi = g_xg[xrow + jB]       + a.x;
                float gf = g_xg[xrow + 256 + jB] + a.y;
                float gm = g_xg[xrow + 512 + jB] + a.z;
                float go = g_xg[xrow + 768 + jB] + a.w;
                float cm = 0.f;
#pragma unroll
                for (int k = 1; k <= 4; k++)
                    cm += sWts[lr][3 + k] * __ldcg(&g_C[((t - k) & 7) * RSZ + row * U_ + jB]);
                cm = fmaxf(cm, 0.f);
                float c = hsig(gf) * cm + hsig(gi) * hsig(gm);
                float h = hsig(go) * tanhf(c);
                g_H[slot * RSZ + row * U_ + jB] = h;
                g_C[slot * RSZ + row * U_ + jB] = c;
                g_outs[((size_t)bb * T_ + td) * 512 + dir * 256 + jB] = h;
            }
        }
        gridbar(2u * (unsigned)t + 1u);

        // ===== Phase CQ: Q products (f32x2) + pipelined scores for t+1 ========
        {
            float* sHf = (float*)sH2;
            float* sCf = (float*)sC2;
            for (int i = tid; i < 4096; i += 256) {
                int r = i >> 8, k = i & 255;
                int idx = ((r & 7) * 264 + k) * 2 + (r >> 3);
                sHf[idx] = __ldcg(&g_H[slot * RSZ + (R0 + r) * U_ + k]);
                sCf[idx] = __ldcg(&g_C[slot * RSZ + (R0 + r) * U_ + k]);
            }
        }
        __syncthreads();
        {
            const ull* h2p = sH2 + rr * 264;
            const ull* c2p = sC2 + rr * 264;
            ull aH2 = 0ull, aCH2 = 0ull, aC2 = 0ull;
#pragma unroll 4
            for (int k = 0; k < U_; k++) {
                float2 w = __ldg(&g_att2[k * U_ + jB]);
                ull wxx = pack2(w.x, w.x);
                ull wyy = pack2(w.y, w.y);
                ull h2 = h2p[k], c2 = c2p[k];
                aH2  = fma2(h2, wxx, aH2);
                aCH2 = fma2(c2, wxx, aCH2);
                aC2  = fma2(c2, wyy, aC2);
            }
            float aH0, aH1, aCH0, aCH1, aC0, aC1;
            unpack2(aH2, aH0, aH1); unpack2(aCH2, aCH0, aCH1); unpack2(aC2, aC0, aC1);
            int b0 = slot * RSZ + (R0 + rr) * U_ + jB;
            int b1 = slot * RSZ + (R0 + rr + 8) * U_ + jB;
            g_QH[b0] = aH0;  g_QC4H[b0] = aCH0;  g_QC[b0] = aC0;
            g_QH[b1] = aH1;  g_QC4H[b1] = aCH1;  g_QC[b1] = aC1;

            // ---- scores for step t+1: k=1 fresh (registers), k=2..4 from ring
            if (t < T_ - 1) {
                const int s1 = (t - 1) & 7, s2 = (t - 2) & 7, s3 = (t - 3) & 7;
#pragma unroll
                for (int pr = 0; pr < 2; pr++) {
                    const int lr = rr + pr * 8;
                    const int row = R0 + lr;
                    const int dir = row >> 7, bb = row & 127;
                    const int td1 = dir ? (T_ - 2 - t) : (t + 1);
                    const size_t xb = (size_t)(td1 * B_ + bb) * U_ + jB;
                    const float xh = g_xh[xb], xc = g_xc[xb];
                    const int ro = row * U_ + jB;
                    float v[8];
                    v[0] = t2((pr ? aH1 : aH0) + xh);
                    v[1] = t2(__ldcg(&g_QH[s1 * RSZ + ro]) + xh);
                    v[2] = t2(__ldcg(&g_QH[s2 * RSZ + ro]) + xh);
                    v[3] = t2(__ldcg(&g_QH[s3 * RSZ + ro]) + xh);
                    v[4] = t2((pr ? aC1 : aC0) + xc);
                    v[5] = t2(__ldcg(&g_QC[s1 * RSZ + ro]) + xc);
                    v[6] = t2(__ldcg(&g_QC[s2 * RSZ + ro]) + xc);
                    v[7] = t2(__ldcg(&g_QC4H[s3 * RSZ + ro]) + xh);  // 4th c uses Wh
#pragma unroll
                    for (int i = 0; i < 8; i++) {
                        v[i] += __shfl_down_sync(0xffffffffu, v[i], 2, 4);
                        v[i] += __shfl_down_sync(0xffffffffu, v[i], 1, 4);
                    }
                    if (jq == 0) {
#pragma unroll
                        for (int i = 0; i < 8; i++) sSw[wid][lr][i] = v[i];
                    }
                }
            }
        }
        __syncthreads();
        if (t < T_ - 1 && tid < 128) {
            int r = tid >> 3, st = tid & 7;
            float s = 0.f;
#pragma unroll
            for (int w = 0; w < 8; w++) s += sSw[w][r][st];
            g_spart[((R0 + r) * 8 + nt) * 8 + st] = s;
        }
        gridbar(2u * (unsigned)t + 2u);
    }
}

// ---------------- final: ha/hb reductions + tanh epilogue ---------------------
__global__ void k_final(const float* __restrict__ att2, const float* __restrict__ att22,
                        float* __restrict__ out) {
    int r = blockIdx.x, j = threadIdx.x;
    float v1 = fmaxf(g_c1[(size_t)r * U_ + j], 0.f) * att2[j];
    float v2 = fmaxf(g_c2[(size_t)r * U_ + j], 0.f) * att22[j];
#pragma unroll
    for (int o = 16; o > 0; o >>= 1) {
        v1 += __shfl_down_sync(0xffffffffu, v1, o);
        v2 += __shfl_down_sync(0xffffffffu, v2, o);
    }
    __shared__ float s1[8], s2[8];
    int lane = j & 31, w = j >> 5;
    if (lane == 0) { s1[w] = v1; s2[w] = v2; }
    __syncthreads();
    if (j == 0) {
        float a = 0.f, bsum = 0.f;
#pragma unroll
        for (int i = 0; i < 8; i++) { a += s1[i]; bsum += s2[i]; }
        s1[0] = a; s2[0] = bsum;
    }
    __syncthreads();
    float ha = s1[0], hb = s2[0];
    size_t base = (size_t)r * 512;
    out[base + j]       = tanhf(ha * g_outs[base + j] + hb);
    out[base + 256 + j] = tanhf(ha * g_outs[base + 256 + j] + hb);
}

// ---------------- launcher ----------------------------------------------------
extern "C" void kernel_launch(void* const* d_in, const int* in_sizes, int n_in,
                              void* d_out, int out_size) {
    // ---- size-driven input mapping (robust to metadata ordering) ----
    int ix = -1, ikern = -1;
    int i262[2] = {-1, -1}, n262 = 0;
    int i196[2] = {-1, -1}, n196 = 0;
    int i256[4] = {-1, -1, -1, -1}, n256 = 0;
    for (int i = 0; i < n_in; i++) {
        int s = in_sizes[i];
        if      (s == 33554432) ix = i;
        else if (s == 524288)   ikern = i;
        else if (s == 262144) { if (n262 < 2) i262[n262++] = i; }
        else if (s == 196608) { if (n196 < 2) i196[n196++] = i; }
        else if (s == 256)    { if (n256 < 4) i256[n256++] = i; }
    }
    const bool alpha = (ix != 0);

    const float* x     = (const float*)d_in[ix];
    const float* kern  = (const float*)d_in[ikern];
    const float* rk    = (const float*)d_in[alpha ? i262[1] : i262[0]];
    const float* att1  = (const float*)d_in[alpha ? i262[0] : i262[1]];
    const float* att_h = (const float*)d_in[alpha ? i196[1] : i196[0]];
    const float* att_c = (const float*)d_in[alpha ? i196[0] : i196[1]];
    const float* att2  = (const float*)d_in[alpha ? i256[0] : i256[1]];
    const float* att22 = (const float*)d_in[alpha ? i256[1] : i256[2]];
    float* out = (float*)d_out;

    // resolve real device addresses of __device__ globals
    float *xT_p, *xg_p, *xh_p, *xc_p, *outs_p, *c1_p, *c2_p;
    cudaGetSymbolAddress((void**)&xT_p,   g_xT);
    cudaGetSymbolAddress((void**)&xg_p,   g_xg);
    cudaGetSymbolAddress((void**)&xh_p,   g_xh);
    cudaGetSymbolAddress((void**)&xc_p,   g_xc);
    cudaGetSymbolAddress((void**)&outs_p, g_outs);
    cudaGetSymbolAddress((void**)&c1_p,   g_c1);
    cudaGetSymbolAddress((void**)&c2_p,   g_c2);

    static const int kRecurSmem = 131072 + 2 * 16896;   // 164864 B
    cudaFuncSetAttribute(k_recur, cudaFuncAttributeMaxDynamicSharedMemorySize, kRecurSmem);

    k_zero<<<(RING * RSZ + 1023) / 1024, 1024>>>();
    k_permute<<<NROW, 128>>>(x);
    k_prep_rk<<<U_, U_>>>(rk);
    k_prep_att<<<U_, U_>>>(att_h, att_c);

    // precompute GEMMs: xg = xT@kernel, xh/xc = xT @ (x-halves of Wh/Wc)
    k_sgemm<<<dim3(1024 / 128, NROW / 128), 256>>>(xT_p, kern,              xg_p, NROW, 1024, 512, F_, 1024);
    k_sgemm<<<dim3(256 / 128,  NROW / 128), 256>>>(xT_p, att_h + 256 * 256, xh_p, NROW, 256, 512, F_, 256);
    k_sgemm<<<dim3(256 / 128,  NROW / 128), 256>>>(xT_p, att_c + 256 * 256, xc_p, NROW, 256, 512, F_, 256);

    // t=0 score partials (states zero => scores from x parts only)
    k_initss<<<NB, U_>>>();

    // persistent bidirectional recurrence (2 barriers/step, f32x2 math)
    k_recur<<<NCTA, 256, kRecurSmem>>>();

    // final stage: c1 = outs@A11, c2 = x@A12, fused reduce + tanh
    k_sgemm<<<dim3(256 / 128, NROW / 128), 256>>>(outs_p, att1,             c1_p, NROW, 256, 512, 512, 256);
    k_sgemm<<<dim3(256 / 128, NROW / 128), 256>>>(x,      att1 + 512 * 256, c2_p, NROW, 256, 512, 512, 256);
    k_final<<<NROW, U_>>>(att2, att22, out);
}